// round 5
// baseline (speedup 1.0000x reference)
#include <cuda_runtime.h>
#include <cuda_bf16.h>
#include <math.h>
#include <stdint.h>

#define NN 200000
#define NE 400000

// ---------------- scratch (static device memory) -----------------------------
__device__ float g_agg[(size_t)NN * 64];
__device__ __nv_bfloat16 g_xh[(size_t)NN * 128],  g_xl[(size_t)NN * 128];
__device__ __nv_bfloat16 g_x1h[(size_t)NN * 128], g_x1l[(size_t)NN * 128];
__device__ __nv_bfloat16 g_x2h[(size_t)NN * 128], g_x2l[(size_t)NN * 128];
__device__ __nv_bfloat16 g_aggh[(size_t)NN * 64], g_aggl[(size_t)NN * 64];
__device__ __nv_bfloat16 g_eah[(size_t)NE * 128], g_eal[(size_t)NE * 128];
// transposed + hi/lo-split weights: layout [n=128][K] row-major
__device__ __nv_bfloat16 g_c1h[192 * 128], g_c1l[192 * 128];
__device__ __nv_bfloat16 g_c2h[128 * 128], g_c2l[128 * 128];
__device__ __nv_bfloat16 g_c3h[128 * 128], g_c3l[128 * 128];
__device__ __nv_bfloat16 g_e1h[384 * 128], g_e1l[384 * 128];
__device__ __nv_bfloat16 g_e2h[128 * 128], g_e2l[128 * 128];
__device__ __nv_bfloat16 g_e3h[128 * 128], g_e3l[128 * 128];

// ---------------- smem map (relative to 1024-aligned base) -------------------
// A stages: 2 x (H 16K + L 16K); B stages: 2 x (H 16K + L 16K)
#define SM_AH0 0
#define SM_AL0 16384
#define SM_AH1 32768
#define SM_AL1 49152
#define SM_BH0 65536
#define SM_BL0 81920
#define SM_BH1 98304
#define SM_BL1 114688
#define SM_LN  65536            /* float2 part[2][128], reuses B0 region */
#define SM_SIDX 131072          /* edge: 256 ints */
#define SMEM_ALLOC (131072 + 1024 + 1024)

static __device__ __forceinline__ uint32_t smem_u32(const void* p) {
    uint32_t a;
    asm("{ .reg .u64 t; cvta.to.shared.u64 t, %1; cvt.u32.u64 %0, t; }" : "=r"(a) : "l"(p));
    return a;
}
static __device__ __forceinline__ uint32_t swz(uint32_t o) { return o ^ ((o >> 3) & 0x70); }

static __device__ __forceinline__ void ldsm4(uint32_t r[4], uint32_t addr) {
    asm volatile("ldmatrix.sync.aligned.m8n8.x4.shared.b16 {%0,%1,%2,%3}, [%4];"
                 : "=r"(r[0]), "=r"(r[1]), "=r"(r[2]), "=r"(r[3]) : "r"(addr));
}
static __device__ __forceinline__ void mma_bf16(float c[4], const uint32_t a[4], const uint32_t b[2]) {
    asm volatile(
        "mma.sync.aligned.m16n8k16.row.col.f32.bf16.bf16.f32 "
        "{%0,%1,%2,%3}, {%4,%5,%6,%7}, {%8,%9}, {%0,%1,%2,%3};"
        : "+f"(c[0]), "+f"(c[1]), "+f"(c[2]), "+f"(c[3])
        : "r"(a[0]), "r"(a[1]), "r"(a[2]), "r"(a[3]), "r"(b[0]), "r"(b[1]));
}
static __device__ __forceinline__ void cpa16(uint32_t dst, const void* src, uint32_t sz) {
    asm volatile("cp.async.cg.shared.global [%0], [%1], 16, %2;"
                 :: "r"(dst), "l"(src), "r"(sz) : "memory");
}
static __device__ __forceinline__ void cpa_commit() {
    asm volatile("cp.async.commit_group;" ::: "memory");
}
static __device__ __forceinline__ void cpa_wait0() {
    asm volatile("cp.async.wait_group 0;" ::: "memory");
}
static __device__ __forceinline__ void cpa_wait1() {
    asm volatile("cp.async.wait_group 1;" ::: "memory");
}

// ---------------- async tile loaders (256 threads) ---------------------------
// B chunk: global [128 n][K] bf16 (hi/lo) -> smem stage [128 n][64 k] SW128
static __device__ __forceinline__ void loadB_async(
    uint32_t sb, int obh, int obl,
    const __nv_bfloat16* __restrict__ Bh, const __nv_bfloat16* __restrict__ Bl, int K, int c)
{
    int t = threadIdx.x, seg = t & 7, r0 = t >> 3;
    const __nv_bfloat16* bh = Bh + c * 64 + seg * 8;
    const __nv_bfloat16* bl = Bl + c * 64 + seg * 8;
#pragma unroll
    for (int p = 0; p < 4; p++) {
        int n = p * 32 + r0;
        uint32_t off = swz((uint32_t)(n * 128 + seg * 16));
        cpa16(sb + obh + off, bh + (size_t)n * K, 16u);
        cpa16(sb + obl + off, bl + (size_t)n * K, 16u);
    }
}

// ---------------- warp GEMM over one 64-k chunk ------------------------------
// Reordered into 3 term passes per k-step: same-accumulator reuse distance = 16 MMAs.
static __device__ __forceinline__ void compute_chunk(
    uint32_t sb, int oah, int oal, int obh, int obl,
    float acc[2][8][4], int wm, int wn, int lane)
{
#pragma unroll
    for (int kk = 0; kk < 4; kk++) {
        uint32_t ah[2][4], al[2][4];
        int rowA = wm * 32 + (lane & 15);
        int kbA = kk * 32 + (lane >> 4) * 16;
#pragma unroll
        for (int mf = 0; mf < 2; mf++) {
            uint32_t o = swz((uint32_t)((rowA + mf * 16) * 128 + kbA));
            ldsm4(ah[mf], sb + oah + o);
            ldsm4(al[mf], sb + oal + o);
        }
        uint32_t bh[4][4], bl[4][4];
        int rowB = wn * 64 + ((lane >> 4) & 1) * 8 + (lane & 7);
        int kbB = kk * 32 + ((lane >> 3) & 1) * 16;
#pragma unroll
        for (int ng = 0; ng < 4; ng++) {
            uint32_t o = swz((uint32_t)((rowB + ng * 16) * 128 + kbB));
            ldsm4(bh[ng], sb + obh + o);
            ldsm4(bl[ng], sb + obl + o);
        }
        // pass 1: ah * bh
#pragma unroll
        for (int ng = 0; ng < 4; ng++)
#pragma unroll
            for (int mf = 0; mf < 2; mf++) {
                mma_bf16(acc[mf][ng * 2],     ah[mf], bh[ng]);
                mma_bf16(acc[mf][ng * 2 + 1], ah[mf], bh[ng] + 2);
            }
        // pass 2: al * bh
#pragma unroll
        for (int ng = 0; ng < 4; ng++)
#pragma unroll
            for (int mf = 0; mf < 2; mf++) {
                mma_bf16(acc[mf][ng * 2],     al[mf], bh[ng]);
                mma_bf16(acc[mf][ng * 2 + 1], al[mf], bh[ng] + 2);
            }
        // pass 3: ah * bl
#pragma unroll
        for (int ng = 0; ng < 4; ng++)
#pragma unroll
            for (int mf = 0; mf < 2; mf++) {
                mma_bf16(acc[mf][ng * 2],     ah[mf], bl[ng]);
                mma_bf16(acc[mf][ng * 2 + 1], ah[mf], bl[ng] + 2);
            }
    }
}

static __device__ __forceinline__ void zero_acc(float acc[2][8][4]) {
#pragma unroll
    for (int mf = 0; mf < 2; mf++)
#pragma unroll
        for (int nf = 0; nf < 8; nf++)
#pragma unroll
            for (int j = 0; j < 4; j++) acc[mf][nf][j] = 0.f;
}

// ---------------- epilogues --------------------------------------------------
// bias + SiLU, split hi/lo, store act: cols 0-63 -> A stage0, cols 64-127 -> A stage1.
// Caller provides surrounding barriers.
static __device__ __forceinline__ void epi_silu(
    char* smA, float acc[2][8][4], const float* __restrict__ bias, int wm, int wn, int lane)
{
    int oh = wn ? SM_AH1 : SM_AH0;
    int ol = wn ? SM_AL1 : SM_AL0;
#pragma unroll
    for (int mf = 0; mf < 2; mf++)
#pragma unroll
        for (int nf = 0; nf < 8; nf++) {
            int colin = nf * 8 + (lane & 3) * 2;      // within 64-col half
            int col = wn * 64 + colin;
            float b0 = __ldg(bias + col), b1 = __ldg(bias + col + 1);
#pragma unroll
            for (int h = 0; h < 2; h++) {
                float v0 = acc[mf][nf][2 * h]     + b0;
                float v1 = acc[mf][nf][2 * h + 1] + b1;
                v0 = v0 / (1.f + __expf(-v0));
                v1 = v1 / (1.f + __expf(-v1));
                __nv_bfloat162 hh = __floats2bfloat162_rn(v0, v1);
                float2 hf = __bfloat1622float2(hh);
                __nv_bfloat162 ll = __floats2bfloat162_rn(v0 - hf.x, v1 - hf.y);
                int row = wm * 32 + mf * 16 + (lane >> 2) + h * 8;
                uint32_t off = swz((uint32_t)(row * 128 + colin * 2));
                *reinterpret_cast<uint32_t*>(smA + oh + off) = *reinterpret_cast<uint32_t*>(&hh);
                *reinterpret_cast<uint32_t*>(smA + ol + off) = *reinterpret_cast<uint32_t*>(&ll);
            }
        }
}

// bias + LayerNorm; optional bf16 hi/lo output and fp32 resid+LN output.
static __device__ __forceinline__ void epi_ln(
    char* smA, float acc[2][8][4],
    const float* __restrict__ b3, const float* __restrict__ gam, const float* __restrict__ bet,
    __nv_bfloat16* __restrict__ outh, __nv_bfloat16* __restrict__ outl,
    const float* __restrict__ resid, float* __restrict__ outf,
    long row0, long limit, int wm, int wn, int lane)
{
    float2* part = reinterpret_cast<float2*>(smA + SM_LN);   // [2][128]
    float ps[2][2], ps2[2][2];
#pragma unroll
    for (int mf = 0; mf < 2; mf++)
#pragma unroll
        for (int h = 0; h < 2; h++) { ps[mf][h] = 0.f; ps2[mf][h] = 0.f; }
#pragma unroll
    for (int mf = 0; mf < 2; mf++)
#pragma unroll
        for (int nf = 0; nf < 8; nf++) {
            int col = wn * 64 + nf * 8 + (lane & 3) * 2;
            float b0 = __ldg(b3 + col), b1 = __ldg(b3 + col + 1);
#pragma unroll
            for (int h = 0; h < 2; h++) {
                float v0 = acc[mf][nf][2 * h] + b0;     acc[mf][nf][2 * h] = v0;
                float v1 = acc[mf][nf][2 * h + 1] + b1; acc[mf][nf][2 * h + 1] = v1;
                ps[mf][h] += v0 + v1;
                ps2[mf][h] += v0 * v0 + v1 * v1;
            }
        }
#pragma unroll
    for (int mf = 0; mf < 2; mf++)
#pragma unroll
        for (int h = 0; h < 2; h++) {
            ps[mf][h]  += __shfl_xor_sync(0xffffffffu, ps[mf][h], 1);
            ps2[mf][h] += __shfl_xor_sync(0xffffffffu, ps2[mf][h], 1);
            ps[mf][h]  += __shfl_xor_sync(0xffffffffu, ps[mf][h], 2);
            ps2[mf][h] += __shfl_xor_sync(0xffffffffu, ps2[mf][h], 2);
        }
    if ((lane & 3) == 0) {
#pragma unroll
        for (int mf = 0; mf < 2; mf++)
#pragma unroll
            for (int h = 0; h < 2; h++) {
                int row = wm * 32 + mf * 16 + (lane >> 2) + h * 8;
                part[wn * 128 + row] = make_float2(ps[mf][h], ps2[mf][h]);
            }
    }
    __syncthreads();
    float mn[2][2], rs[2][2];
#pragma unroll
    for (int mf = 0; mf < 2; mf++)
#pragma unroll
        for (int h = 0; h < 2; h++) {
            int row = wm * 32 + mf * 16 + (lane >> 2) + h * 8;
            float2 o = part[(1 - wn) * 128 + row];
            float s = ps[mf][h] + o.x, s2 = ps2[mf][h] + o.y;
            float mean = s * (1.f / 128.f);
            float var = s2 * (1.f / 128.f) - mean * mean;
            mn[mf][h] = mean;
            rs[mf][h] = rsqrtf(var + 1e-5f);
        }
#pragma unroll
    for (int mf = 0; mf < 2; mf++)
#pragma unroll
        for (int nf = 0; nf < 8; nf++) {
            int col = wn * 64 + nf * 8 + (lane & 3) * 2;
            float g0 = __ldg(gam + col), g1 = __ldg(gam + col + 1);
            float e0 = __ldg(bet + col), e1 = __ldg(bet + col + 1);
#pragma unroll
            for (int h = 0; h < 2; h++) {
                int row = wm * 32 + mf * 16 + (lane >> 2) + h * 8;
                long gr = row0 + row;
                if (gr >= limit) continue;
                float o0 = (acc[mf][nf][2 * h]     - mn[mf][h]) * rs[mf][h] * g0 + e0;
                float o1 = (acc[mf][nf][2 * h + 1] - mn[mf][h]) * rs[mf][h] * g1 + e1;
                if (outh) {
                    __nv_bfloat162 hh = __floats2bfloat162_rn(o0, o1);
                    float2 hf = __bfloat1622float2(hh);
                    __nv_bfloat162 ll = __floats2bfloat162_rn(o0 - hf.x, o1 - hf.y);
                    *reinterpret_cast<__nv_bfloat162*>(outh + gr * 128 + col) = hh;
                    *reinterpret_cast<__nv_bfloat162*>(outl + gr * 128 + col) = ll;
                }
                if (outf) {
                    float2 rv = *reinterpret_cast<const float2*>(resid + gr * 128 + col);
                    *reinterpret_cast<float2*>(outf + gr * 128 + col) = make_float2(o0 + rv.x, o1 + rv.y);
                }
            }
        }
}

// ---------------- cell (node) MLP kernel -------------------------------------
__global__ void __launch_bounds__(256) cell_kernel(
    const __nv_bfloat16* __restrict__ xh, const __nv_bfloat16* __restrict__ xl,
    const float* __restrict__ b1, const float* __restrict__ b2, const float* __restrict__ b3,
    const float* __restrict__ gam, const float* __restrict__ bet,
    __nv_bfloat16* __restrict__ outh, __nv_bfloat16* __restrict__ outl,
    const float* __restrict__ resid, float* __restrict__ outf)
{
    extern __shared__ char smraw[];
    uint32_t sb0 = smem_u32(smraw);
    uint32_t sb = (sb0 + 1023u) & ~1023u;
    char* smA = smraw + (sb - sb0);
    int tid = threadIdx.x, lane = tid & 31, wid = tid >> 5;
    int wm = wid >> 1, wn = wid & 1;
    long row0 = (long)blockIdx.x * 128;

    auto issueA = [&](int c, int oah, int oal) {
        int seg = tid & 7, r0 = tid >> 3;
#pragma unroll
        for (int p = 0; p < 4; p++) {
            int r = p * 32 + r0;
            long gr = row0 + r;
            bool v = gr < NN;
            const __nv_bfloat16 *ph, *pl;
            if (c < 2) {
                size_t o = v ? ((size_t)gr * 128 + (size_t)c * 64 + seg * 8) : 0;
                ph = xh + o; pl = xl + o;
            } else {
                size_t o = v ? ((size_t)gr * 64 + seg * 8) : 0;
                ph = g_aggh + o; pl = g_aggl + o;
            }
            uint32_t off = swz((uint32_t)(r * 128 + seg * 16));
            cpa16(sb + oah + off, ph, v ? 16u : 0u);
            cpa16(sb + oal + off, pl, v ? 16u : 0u);
        }
    };

    float acc[2][8][4];
    zero_acc(acc);

    // prologue: chunks 0,1 in flight
    issueA(0, SM_AH0, SM_AL0); loadB_async(sb, SM_BH0, SM_BL0, g_c1h, g_c1l, 192, 0); cpa_commit();
    issueA(1, SM_AH1, SM_AL1); loadB_async(sb, SM_BH1, SM_BL1, g_c1h, g_c1l, 192, 1); cpa_commit();
    // c0
    cpa_wait1(); __syncthreads();
    compute_chunk(sb, SM_AH0, SM_AL0, SM_BH0, SM_BL0, acc, wm, wn, lane);
    __syncthreads();
    issueA(2, SM_AH0, SM_AL0); loadB_async(sb, SM_BH0, SM_BL0, g_c1h, g_c1l, 192, 2); cpa_commit();
    // c1
    cpa_wait1(); __syncthreads();
    compute_chunk(sb, SM_AH1, SM_AL1, SM_BH1, SM_BL1, acc, wm, wn, lane);
    __syncthreads();
    loadB_async(sb, SM_BH1, SM_BL1, g_c2h, g_c2l, 128, 0); cpa_commit();   // L2 c0
    // c2
    cpa_wait1(); __syncthreads();
    compute_chunk(sb, SM_AH0, SM_AL0, SM_BH0, SM_BL0, acc, wm, wn, lane);
    __syncthreads();
    loadB_async(sb, SM_BH0, SM_BL0, g_c2h, g_c2l, 128, 1); cpa_commit();   // L2 c1
    // L1 epilogue -> act in A stages
    epi_silu(smA, acc, b1, wm, wn, lane);
    zero_acc(acc);
    // c3 = L2 c0: A st0, B st1
    cpa_wait1(); __syncthreads();
    compute_chunk(sb, SM_AH0, SM_AL0, SM_BH1, SM_BL1, acc, wm, wn, lane);
    __syncthreads();
    loadB_async(sb, SM_BH1, SM_BL1, g_c3h, g_c3l, 128, 0); cpa_commit();   // L3 c0
    // c4 = L2 c1: A st1, B st0
    cpa_wait1(); __syncthreads();
    compute_chunk(sb, SM_AH1, SM_AL1, SM_BH0, SM_BL0, acc, wm, wn, lane);
    __syncthreads();
    loadB_async(sb, SM_BH0, SM_BL0, g_c3h, g_c3l, 128, 1); cpa_commit();   // L3 c1
    // L2 epilogue
    epi_silu(smA, acc, b2, wm, wn, lane);
    zero_acc(acc);
    // c5 = L3 c0: A st0, B st1
    cpa_wait1(); __syncthreads();
    compute_chunk(sb, SM_AH0, SM_AL0, SM_BH1, SM_BL1, acc, wm, wn, lane);
    __syncthreads();
    // c6 = L3 c1: A st1, B st0
    cpa_wait0(); __syncthreads();
    compute_chunk(sb, SM_AH1, SM_AL1, SM_BH0, SM_BL0, acc, wm, wn, lane);
    __syncthreads();
    epi_ln(smA, acc, b3, gam, bet, outh, outl, resid, outf, row0, NN, wm, wn, lane);
}

// ---------------- edge MLP kernel --------------------------------------------
__global__ void __launch_bounds__(256) edge_kernel(
    const __nv_bfloat16* __restrict__ eah, const __nv_bfloat16* __restrict__ eal,
    const __nv_bfloat16* __restrict__ x2h, const __nv_bfloat16* __restrict__ x2l,
    const int* __restrict__ snd, const int* __restrict__ rcv,
    const float* __restrict__ b1, const float* __restrict__ b2, const float* __restrict__ b3,
    const float* __restrict__ gam, const float* __restrict__ bet,
    const float* __restrict__ ea_resid, float* __restrict__ outf)
{
    extern __shared__ char smraw[];
    uint32_t sb0 = smem_u32(smraw);
    uint32_t sb = (sb0 + 1023u) & ~1023u;
    char* smA = smraw + (sb - sb0);
    int tid = threadIdx.x, lane = tid & 31, wid = tid >> 5;
    int wm = wid >> 1, wn = wid & 1;
    long row0 = (long)blockIdx.x * 128;

    int* sidx = reinterpret_cast<int*>(smA + SM_SIDX);
    if (tid < 128) sidx[tid] = snd[row0 + tid];
    else           sidx[tid] = rcv[row0 + tid - 128];

    auto issueA = [&](int c, int oah, int oal) {
        int seg = tid & 7, r0 = tid >> 3;
#pragma unroll
        for (int p = 0; p < 4; p++) {
            int r = p * 32 + r0;
            size_t o;
            const __nv_bfloat16 *ph, *pl;
            if (c < 2) {
                o = (size_t)(row0 + r) * 128 + (size_t)c * 64 + seg * 8;
                ph = eah + o; pl = eal + o;
            } else {
                int node = sidx[(c >= 4 ? 128 : 0) + r];
                o = (size_t)node * 128 + (size_t)(c & 1) * 64 + seg * 8;
                ph = x2h + o; pl = x2l + o;
            }
            uint32_t off = swz((uint32_t)(r * 128 + seg * 16));
            cpa16(sb + oah + off, ph, 16u);
            cpa16(sb + oal + off, pl, 16u);
        }
    };

    float acc[2][8][4];
    zero_acc(acc);

    // prologue (chunks 0,1 use only ea -> no sidx dependency)
    issueA(0, SM_AH0, SM_AL0); loadB_async(sb, SM_BH0, SM_BL0, g_e1h, g_e1l, 384, 0); cpa_commit();
    issueA(1, SM_AH1, SM_AL1); loadB_async(sb, SM_BH1, SM_BL1, g_e1h, g_e1l, 384, 1); cpa_commit();
    // c0..c3 (prefetch c+2; sidx visible after first sync)
#pragma unroll 1
    for (int c = 0; c < 4; c++) {
        int st = c & 1;
        cpa_wait1(); __syncthreads();
        compute_chunk(sb, st ? SM_AH1 : SM_AH0, st ? SM_AL1 : SM_AL0,
                      st ? SM_BH1 : SM_BH0, st ? SM_BL1 : SM_BL0, acc, wm, wn, lane);
        __syncthreads();
        issueA(c + 2, st ? SM_AH1 : SM_AH0, st ? SM_AL1 : SM_AL0);
        loadB_async(sb, st ? SM_BH1 : SM_BH0, st ? SM_BL1 : SM_BL0, g_e1h, g_e1l, 384, c + 2);
        cpa_commit();
    }
    // c4
    cpa_wait1(); __syncthreads();
    compute_chunk(sb, SM_AH0, SM_AL0, SM_BH0, SM_BL0, acc, wm, wn, lane);
    __syncthreads();
    loadB_async(sb, SM_BH0, SM_BL0, g_e2h, g_e2l, 128, 0); cpa_commit();   // L2 c0
    // c5
    cpa_wait1(); __syncthreads();
    compute_chunk(sb, SM_AH1, SM_AL1, SM_BH1, SM_BL1, acc, wm, wn, lane);
    __syncthreads();
    loadB_async(sb, SM_BH1, SM_BL1, g_e2h, g_e2l, 128, 1); cpa_commit();   // L2 c1
    // L1 epilogue
    epi_silu(smA, acc, b1, wm, wn, lane);
    zero_acc(acc);
    // c6 = L2 c0
    cpa_wait1(); __syncthreads();
    compute_chunk(sb, SM_AH0, SM_AL0, SM_BH0, SM_BL0, acc, wm, wn, lane);
    __syncthreads();
    loadB_async(sb, SM_BH0, SM_BL0, g_e3h, g_e3l, 128, 0); cpa_commit();   // L3 c0
    // c7 = L2 c1
    cpa_wait1(); __syncthreads();
    compute_chunk(sb, SM_AH1, SM_AL1, SM_BH1, SM_BL1, acc, wm, wn, lane);
    __syncthreads();
    loadB_async(sb, SM_BH1, SM_BL1, g_e3h, g_e3l, 128, 1); cpa_commit();   // L3 c1
    // L2 epilogue
    epi_silu(smA, acc, b2, wm, wn, lane);
    zero_acc(acc);
    // c8 = L3 c0
    cpa_wait1(); __syncthreads();
    compute_chunk(sb, SM_AH0, SM_AL0, SM_BH0, SM_BL0, acc, wm, wn, lane);
    __syncthreads();
    // c9 = L3 c1
    cpa_wait0(); __syncthreads();
    compute_chunk(sb, SM_AH1, SM_AL1, SM_BH1, SM_BL1, acc, wm, wn, lane);
    __syncthreads();
    epi_ln(smA, acc, b3, gam, bet, nullptr, nullptr, ea_resid, outf, row0, NE, wm, wn, lane);
}

// ---------------- scatter + conversions + weight prep ------------------------
// single fused weight-prep launch: grid.y = job index
struct WJobs {
    const float* src[6];
    __nv_bfloat16* h[6];
    __nv_bfloat16* l[6];
    int K[6];
};
__global__ void wconv_all_kernel(WJobs jobs) {
    int j = blockIdx.y;
    int K = jobs.K[j];
    int i = blockIdx.x * blockDim.x + threadIdx.x;
    if (i >= 128 * K) return;
    int n = i / K, k = i - n * K;
    float w = jobs.src[j][(size_t)k * 128 + n];
    __nv_bfloat16 h = __float2bfloat16(w);
    jobs.h[j][i] = h;
    jobs.l[j][i] = __float2bfloat16(w - __bfloat162float(h));
}

__global__ void zero_agg_kernel() {
    size_t n = (size_t)NN * 64 / 4;
    for (size_t i = (size_t)blockIdx.x * blockDim.x + threadIdx.x; i < n;
         i += (size_t)gridDim.x * blockDim.x)
        reinterpret_cast<float4*>(g_agg)[i] = make_float4(0.f, 0.f, 0.f, 0.f);
}

// scatter + fused ea -> bf16 hi/lo conversion
__global__ void __launch_bounds__(256) scatter_kernel(
    const float* __restrict__ ea, const int* __restrict__ snd, const int* __restrict__ rcv,
    __nv_bfloat16* __restrict__ eah, __nv_bfloat16* __restrict__ eal)
{
    long t = (long)blockIdx.x * blockDim.x + threadIdx.x;
    if (t >= (long)NE * 128) return;
    int e = (int)(t >> 7);
    int c = (int)(t & 127);
    float v = ea[t];
    __nv_bfloat16 h = __float2bfloat16(v);
    eah[t] = h;
    eal[t] = __float2bfloat16(v - __bfloat162float(h));
    if (c < 64) atomicAdd(&g_agg[(size_t)rcv[e] * 64 + c], v);
    else        atomicAdd(&g_agg[(size_t)snd[e] * 64 + (c - 64)], v);
}

// fp32 -> bf16 hi/lo split (pairs)
__global__ void conv_hl_kernel(const float* __restrict__ src,
                               __nv_bfloat16* __restrict__ h, __nv_bfloat16* __restrict__ l, long n2)
{
    long i = (long)blockIdx.x * blockDim.x + threadIdx.x;
    if (i >= n2) return;
    float2 v = reinterpret_cast<const float2*>(src)[i];
    __nv_bfloat162 hh = __floats2bfloat162_rn(v.x, v.y);
    float2 hf = __bfloat1622float2(hh);
    __nv_bfloat162 ll = __floats2bfloat162_rn(v.x - hf.x, v.y - hf.y);
    reinterpret_cast<__nv_bfloat162*>(h)[i] = hh;
    reinterpret_cast<__nv_bfloat162*>(l)[i] = ll;
}

// ---------------- launch -----------------------------------------------------
extern "C" void kernel_launch(void* const* d_in, const int* in_sizes, int n_in,
                              void* d_out, int out_size)
{
    const float* x       = (const float*)d_in[0];
    const float* ea      = (const float*)d_in[1];
    const float* cb_w1   = (const float*)d_in[2];
    const float* cb_b1   = (const float*)d_in[3];
    const float* cb_w2   = (const float*)d_in[4];
    const float* cb_b2   = (const float*)d_in[5];
    const float* cb_w3   = (const float*)d_in[6];
    const float* cb_b3   = (const float*)d_in[7];
    const float* cb_g    = (const float*)d_in[8];
    const float* cb_beta = (const float*)d_in[9];
    const float* eb_w1   = (const float*)d_in[10];
    const float* eb_b1   = (const float*)d_in[11];
    const float* eb_w2   = (const float*)d_in[12];
    const float* eb_b2   = (const float*)d_in[13];
    const float* eb_w3   = (const float*)d_in[14];
    const float* eb_b3   = (const float*)d_in[15];
    const float* eb_g    = (const float*)d_in[16];
    const float* eb_beta = (const float*)d_in[17];
    const int*   ei      = (const int*)d_in[18];
    const int* snd = ei;
    const int* rcv = ei + NE;

    float* out_x = (float*)d_out;
    float* out_e = out_x + (size_t)NN * 128;

    float* aggf;
    cudaGetSymbolAddress((void**)&aggf, g_agg);
    __nv_bfloat16 *xh, *xl, *x1h, *x1l, *x2h, *x2l, *aggh, *aggl, *eah, *eal;
    cudaGetSymbolAddress((void**)&xh,  g_xh);  cudaGetSymbolAddress((void**)&xl,  g_xl);
    cudaGetSymbolAddress((void**)&x1h, g_x1h); cudaGetSymbolAddress((void**)&x1l, g_x1l);
    cudaGetSymbolAddress((void**)&x2h, g_x2h); cudaGetSymbolAddress((void**)&x2l, g_x2l);
    cudaGetSymbolAddress((void**)&aggh, g_aggh); cudaGetSymbolAddress((void**)&aggl, g_aggl);
    cudaGetSymbolAddress((void**)&eah, g_eah); cudaGetSymbolAddress((void**)&eal, g_eal);

    WJobs jobs;
    const float* wsrc[6] = {cb_w1, cb_w2, cb_w3, eb_w1, eb_w2, eb_w3};
    int wk[6] = {192, 128, 128, 384, 128, 128};
    __nv_bfloat16* wh[6]; __nv_bfloat16* wl[6];
    cudaGetSymbolAddress((void**)&wh[0], g_c1h); cudaGetSymbolAddress((void**)&wl[0], g_c1l);
    cudaGetSymbolAddress((void**)&wh[1], g_c2h); cudaGetSymbolAddress((void**)&wl[1], g_c2l);
    cudaGetSymbolAddress((void**)&wh[2], g_c3h); cudaGetSymbolAddress((void**)&wl[2], g_c3l);
    cudaGetSymbolAddress((void**)&wh[3], g_e1h); cudaGetSymbolAddress((void**)&wl[3], g_e1l);
    cudaGetSymbolAddress((void**)&wh[4], g_e2h); cudaGetSymbolAddress((void**)&wl[4], g_e2l);
    cudaGetSymbolAddress((void**)&wh[5], g_e3h); cudaGetSymbolAddress((void**)&wl[5], g_e3l);
    for (int j = 0; j < 6; j++) {
        jobs.src[j] = wsrc[j]; jobs.h[j] = wh[j]; jobs.l[j] = wl[j]; jobs.K[j] = wk[j];
    }

    cudaFuncSetAttribute(cell_kernel, cudaFuncAttributeMaxDynamicSharedMemorySize, SMEM_ALLOC);
    cudaFuncSetAttribute(edge_kernel, cudaFuncAttributeMaxDynamicSharedMemorySize, SMEM_ALLOC);

    // launch order chosen so ncu (-s 5 -c 1) captures cell_kernel (launch #6)
    dim3 wgrid((128 * 384 + 255) / 256, 6);
    wconv_all_kernel<<<wgrid, 256>>>(jobs);                                              // 1
    conv_hl_kernel<<<(int)(((long)NN * 64 + 255) / 256), 256>>>(x, xh, xl, (long)NN * 64); // 2
    zero_agg_kernel<<<2048, 256>>>();                                                    // 3
    scatter_kernel<<<(int)(((long)NE * 128 + 255) / 256), 256>>>(ea, snd, rcv, eah, eal); // 4
    conv_hl_kernel<<<(int)(((long)NN * 32 + 255) / 256), 256>>>(aggf, aggh, aggl, (long)NN * 32); // 5

    int cell_grid = (NN + 127) / 128;   // 1563
    int edge_grid = NE / 128;           // 3125

    cell_kernel<<<cell_grid, 256, SMEM_ALLOC>>>(                                         // 6 <- profiled
        xh, xl, cb_b1, cb_b2, cb_b3, cb_g, cb_beta, x1h, x1l, nullptr, nullptr);
    cell_kernel<<<cell_grid, 256, SMEM_ALLOC>>>(
        x1h, x1l, cb_b1, cb_b2, cb_b3, cb_g, cb_beta, x2h, x2l, x, out_x);
    edge_kernel<<<edge_grid, 256, SMEM_ALLOC>>>(
        eah, eal, x2h, x2l, snd, rcv,
        eb_b1, eb_b2, eb_b3, eb_g, eb_beta, ea, out_e);
}

// round 7
// speedup vs baseline: 1.1854x; 1.1854x over previous
#include <cuda_runtime.h>
#include <cuda_bf16.h>
#include <math.h>
#include <stdint.h>

#define NN 200000
#define NE 400000

// ---------------- scratch (static device memory) -----------------------------
__device__ float g_agg[(size_t)NN * 64];
__device__ __nv_bfloat16 g_xh[(size_t)NN * 128],  g_xl[(size_t)NN * 128];
__device__ __nv_bfloat16 g_x1h[(size_t)NN * 128], g_x1l[(size_t)NN * 128];
__device__ __nv_bfloat16 g_x2h[(size_t)NN * 128], g_x2l[(size_t)NN * 128];
__device__ __nv_bfloat16 g_aggh[(size_t)NN * 64], g_aggl[(size_t)NN * 64];
__device__ __nv_bfloat16 g_eah[(size_t)NE * 128], g_eal[(size_t)NE * 128];
// transposed + hi/lo-split weights: layout [n=128][K] row-major
__device__ __nv_bfloat16 g_c1h[192 * 128], g_c1l[192 * 128];
__device__ __nv_bfloat16 g_c2h[128 * 128], g_c2l[128 * 128];
__device__ __nv_bfloat16 g_c3h[128 * 128], g_c3l[128 * 128];
__device__ __nv_bfloat16 g_e1h[384 * 128], g_e1l[384 * 128];
__device__ __nv_bfloat16 g_e2h[128 * 128], g_e2l[128 * 128];
__device__ __nv_bfloat16 g_e3h[128 * 128], g_e3l[128 * 128];

// ---------------- smem map (relative to 1024-aligned base) -------------------
// A stages: 2 x (H 16K + L 16K); B: single stage (H 16K + L 16K) => 96K total
#define SM_A0H 0
#define SM_A0L 16384
#define SM_A1H 32768
#define SM_A1L 49152
#define SM_BH  65536
#define SM_BL  81920
#define SM_LN  65536            /* float2 part[2][128], reuses B region */
#define SM_SIDX 98304           /* edge: 256 ints */
#define SMEM_ALLOC (98304 + 1024 + 1024)

static __device__ __forceinline__ uint32_t smem_u32(const void* p) {
    uint32_t a;
    asm("{ .reg .u64 t; cvta.to.shared.u64 t, %1; cvt.u32.u64 %0, t; }" : "=r"(a) : "l"(p));
    return a;
}
static __device__ __forceinline__ uint32_t swz(uint32_t o) { return o ^ ((o >> 3) & 0x70); }

static __device__ __forceinline__ void ldsm4(uint32_t r[4], uint32_t addr) {
    asm volatile("ldmatrix.sync.aligned.m8n8.x4.shared.b16 {%0,%1,%2,%3}, [%4];"
                 : "=r"(r[0]), "=r"(r[1]), "=r"(r[2]), "=r"(r[3]) : "r"(addr));
}
static __device__ __forceinline__ void mma_bf16(float c[4], const uint32_t a[4], const uint32_t b[2]) {
    asm volatile(
        "mma.sync.aligned.m16n8k16.row.col.f32.bf16.bf16.f32 "
        "{%0,%1,%2,%3}, {%4,%5,%6,%7}, {%8,%9}, {%0,%1,%2,%3};"
        : "+f"(c[0]), "+f"(c[1]), "+f"(c[2]), "+f"(c[3])
        : "r"(a[0]), "r"(a[1]), "r"(a[2]), "r"(a[3]), "r"(b[0]), "r"(b[1]));
}
static __device__ __forceinline__ void cpa16(uint32_t dst, const void* src, uint32_t sz) {
    asm volatile("cp.async.cg.shared.global [%0], [%1], 16, %2;"
                 :: "r"(dst), "l"(src), "r"(sz) : "memory");
}
static __device__ __forceinline__ void cpa_commit() {
    asm volatile("cp.async.commit_group;" ::: "memory");
}
static __device__ __forceinline__ void cpa_wait0() {
    asm volatile("cp.async.wait_group 0;" ::: "memory");
}

// ---------------- async tile loaders (256 threads) ---------------------------
// B chunk: global [128 n][K] bf16 (hi/lo) -> smem [128 n][64 k] SW128
static __device__ __forceinline__ void loadB_async(
    uint32_t sb, const __nv_bfloat16* __restrict__ Bh, const __nv_bfloat16* __restrict__ Bl,
    int K, int c)
{
    int t = threadIdx.x, seg = t & 7, r0 = t >> 3;
    const __nv_bfloat16* bh = Bh + c * 64 + seg * 8;
    const __nv_bfloat16* bl = Bl + c * 64 + seg * 8;
#pragma unroll
    for (int p = 0; p < 4; p++) {
        int n = p * 32 + r0;
        uint32_t off = swz((uint32_t)(n * 128 + seg * 16));
        cpa16(sb + SM_BH + off, bh + (size_t)n * K, 16u);
        cpa16(sb + SM_BL + off, bl + (size_t)n * K, 16u);
    }
}

// ---------------- warp GEMM over one 64-k chunk ------------------------------
// Term-pass ordering: same-accumulator reuse distance = 16 MMAs (no RAW chains).
static __device__ __forceinline__ void compute_chunk(
    uint32_t sb, int oah, int oal, float acc[2][8][4], int wm, int wn, int lane)
{
#pragma unroll
    for (int kk = 0; kk < 4; kk++) {
        uint32_t ah[2][4], al[2][4];
        int rowA = wm * 32 + (lane & 15);
        int kbA = kk * 32 + (lane >> 4) * 16;
#pragma unroll
        for (int mf = 0; mf < 2; mf++) {
            uint32_t o = swz((uint32_t)((rowA + mf * 16) * 128 + kbA));
            ldsm4(ah[mf], sb + oah + o);
            ldsm4(al[mf], sb + oal + o);
        }
        uint32_t bh[4][4], bl[4][4];
        int rowB = wn * 64 + ((lane >> 4) & 1) * 8 + (lane & 7);
        int kbB = kk * 32 + ((lane >> 3) & 1) * 16;
#pragma unroll
        for (int ng = 0; ng < 4; ng++) {
            uint32_t o = swz((uint32_t)((rowB + ng * 16) * 128 + kbB));
            ldsm4(bh[ng], sb + SM_BH + o);
            ldsm4(bl[ng], sb + SM_BL + o);
        }
#pragma unroll
        for (int ng = 0; ng < 4; ng++)
#pragma unroll
            for (int mf = 0; mf < 2; mf++) {
                mma_bf16(acc[mf][ng * 2],     ah[mf], bh[ng]);
                mma_bf16(acc[mf][ng * 2 + 1], ah[mf], bh[ng] + 2);
            }
#pragma unroll
        for (int ng = 0; ng < 4; ng++)
#pragma unroll
            for (int mf = 0; mf < 2; mf++) {
                mma_bf16(acc[mf][ng * 2],     al[mf], bh[ng]);
                mma_bf16(acc[mf][ng * 2 + 1], al[mf], bh[ng] + 2);
            }
#pragma unroll
        for (int ng = 0; ng < 4; ng++)
#pragma unroll
            for (int mf = 0; mf < 2; mf++) {
                mma_bf16(acc[mf][ng * 2],     ah[mf], bl[ng]);
                mma_bf16(acc[mf][ng * 2 + 1], ah[mf], bl[ng] + 2);
            }
    }
}

static __device__ __forceinline__ void zero_acc(float acc[2][8][4]) {
#pragma unroll
    for (int mf = 0; mf < 2; mf++)
#pragma unroll
        for (int nf = 0; nf < 8; nf++)
#pragma unroll
            for (int j = 0; j < 4; j++) acc[mf][nf][j] = 0.f;
}

// ---------------- epilogues --------------------------------------------------
static __device__ __forceinline__ void epi_silu(
    char* smA, float acc[2][8][4], const float* __restrict__ bias, int wm, int wn, int lane)
{
    int oh = wn ? SM_A1H : SM_A0H;
    int ol = wn ? SM_A1L : SM_A0L;
#pragma unroll
    for (int mf = 0; mf < 2; mf++)
#pragma unroll
        for (int nf = 0; nf < 8; nf++) {
            int colin = nf * 8 + (lane & 3) * 2;      // within 64-col half
            int col = wn * 64 + colin;
            float b0 = __ldg(bias + col), b1 = __ldg(bias + col + 1);
#pragma unroll
            for (int h = 0; h < 2; h++) {
                float v0 = acc[mf][nf][2 * h]     + b0;
                float v1 = acc[mf][nf][2 * h + 1] + b1;
                v0 = v0 / (1.f + __expf(-v0));
                v1 = v1 / (1.f + __expf(-v1));
                __nv_bfloat162 hh = __floats2bfloat162_rn(v0, v1);
                float2 hf = __bfloat1622float2(hh);
                __nv_bfloat162 ll = __floats2bfloat162_rn(v0 - hf.x, v1 - hf.y);
                int row = wm * 32 + mf * 16 + (lane >> 2) + h * 8;
                uint32_t off = swz((uint32_t)(row * 128 + colin * 2));
                *reinterpret_cast<uint32_t*>(smA + oh + off) = *reinterpret_cast<uint32_t*>(&hh);
                *reinterpret_cast<uint32_t*>(smA + ol + off) = *reinterpret_cast<uint32_t*>(&ll);
            }
        }
}

static __device__ __forceinline__ void epi_ln(
    char* smA, float acc[2][8][4],
    const float* __restrict__ b3, const float* __restrict__ gam, const float* __restrict__ bet,
    __nv_bfloat16* __restrict__ outh, __nv_bfloat16* __restrict__ outl,
    const float* __restrict__ resid, float* __restrict__ outf,
    long row0, long limit, int wm, int wn, int lane)
{
    float2* part = reinterpret_cast<float2*>(smA + SM_LN);   // [2][128]
    float ps[2][2], ps2[2][2];
#pragma unroll
    for (int mf = 0; mf < 2; mf++)
#pragma unroll
        for (int h = 0; h < 2; h++) { ps[mf][h] = 0.f; ps2[mf][h] = 0.f; }
#pragma unroll
    for (int mf = 0; mf < 2; mf++)
#pragma unroll
        for (int nf = 0; nf < 8; nf++) {
            int col = wn * 64 + nf * 8 + (lane & 3) * 2;
            float b0 = __ldg(b3 + col), b1 = __ldg(b3 + col + 1);
#pragma unroll
            for (int h = 0; h < 2; h++) {
                float v0 = acc[mf][nf][2 * h] + b0;     acc[mf][nf][2 * h] = v0;
                float v1 = acc[mf][nf][2 * h + 1] + b1; acc[mf][nf][2 * h + 1] = v1;
                ps[mf][h] += v0 + v1;
                ps2[mf][h] += v0 * v0 + v1 * v1;
            }
        }
#pragma unroll
    for (int mf = 0; mf < 2; mf++)
#pragma unroll
        for (int h = 0; h < 2; h++) {
            ps[mf][h]  += __shfl_xor_sync(0xffffffffu, ps[mf][h], 1);
            ps2[mf][h] += __shfl_xor_sync(0xffffffffu, ps2[mf][h], 1);
            ps[mf][h]  += __shfl_xor_sync(0xffffffffu, ps[mf][h], 2);
            ps2[mf][h] += __shfl_xor_sync(0xffffffffu, ps2[mf][h], 2);
        }
    if ((lane & 3) == 0) {
#pragma unroll
        for (int mf = 0; mf < 2; mf++)
#pragma unroll
            for (int h = 0; h < 2; h++) {
                int row = wm * 32 + mf * 16 + (lane >> 2) + h * 8;
                part[wn * 128 + row] = make_float2(ps[mf][h], ps2[mf][h]);
            }
    }
    __syncthreads();
    float mn[2][2], rs[2][2];
#pragma unroll
    for (int mf = 0; mf < 2; mf++)
#pragma unroll
        for (int h = 0; h < 2; h++) {
            int row = wm * 32 + mf * 16 + (lane >> 2) + h * 8;
            float2 o = part[(1 - wn) * 128 + row];
            float s = ps[mf][h] + o.x, s2 = ps2[mf][h] + o.y;
            float mean = s * (1.f / 128.f);
            float var = s2 * (1.f / 128.f) - mean * mean;
            mn[mf][h] = mean;
            rs[mf][h] = rsqrtf(var + 1e-5f);
        }
#pragma unroll
    for (int mf = 0; mf < 2; mf++)
#pragma unroll
        for (int nf = 0; nf < 8; nf++) {
            int col = wn * 64 + nf * 8 + (lane & 3) * 2;
            float g0 = __ldg(gam + col), g1 = __ldg(gam + col + 1);
            float e0 = __ldg(bet + col), e1 = __ldg(bet + col + 1);
#pragma unroll
            for (int h = 0; h < 2; h++) {
                int row = wm * 32 + mf * 16 + (lane >> 2) + h * 8;
                long gr = row0 + row;
                if (gr >= limit) continue;
                float o0 = (acc[mf][nf][2 * h]     - mn[mf][h]) * rs[mf][h] * g0 + e0;
                float o1 = (acc[mf][nf][2 * h + 1] - mn[mf][h]) * rs[mf][h] * g1 + e1;
                if (outh) {
                    __nv_bfloat162 hh = __floats2bfloat162_rn(o0, o1);
                    float2 hf = __bfloat1622float2(hh);
                    __nv_bfloat162 ll = __floats2bfloat162_rn(o0 - hf.x, o1 - hf.y);
                    *reinterpret_cast<__nv_bfloat162*>(outh + gr * 128 + col) = hh;
                    *reinterpret_cast<__nv_bfloat162*>(outl + gr * 128 + col) = ll;
                }
                if (outf) {
                    float2 rv = *reinterpret_cast<const float2*>(resid + gr * 128 + col);
                    *reinterpret_cast<float2*>(outf + gr * 128 + col) = make_float2(o0 + rv.x, o1 + rv.y);
                }
            }
        }
}

// layers 2 & 3 (B loads overlap epilogues at layer boundaries)
static __device__ __forceinline__ void run_l23(
    char* smA, uint32_t sb, float acc[2][8][4],
    const __nv_bfloat16* w2h, const __nv_bfloat16* w2l,
    const __nv_bfloat16* w3h, const __nv_bfloat16* w3l,
    const float* b1, const float* b2, int wm, int wn, int lane)
{
    __syncthreads();
    loadB_async(sb, w2h, w2l, 128, 0); cpa_commit();   // overlaps epi_silu
    epi_silu(smA, acc, b1, wm, wn, lane);
    zero_acc(acc);
    cpa_wait0(); __syncthreads();
    compute_chunk(sb, SM_A0H, SM_A0L, acc, wm, wn, lane);
    __syncthreads();
    loadB_async(sb, w2h, w2l, 128, 1); cpa_commit();
    cpa_wait0(); __syncthreads();
    compute_chunk(sb, SM_A1H, SM_A1L, acc, wm, wn, lane);
    __syncthreads();
    loadB_async(sb, w3h, w3l, 128, 0); cpa_commit();   // overlaps epi_silu
    epi_silu(smA, acc, b2, wm, wn, lane);
    zero_acc(acc);
    cpa_wait0(); __syncthreads();
    compute_chunk(sb, SM_A0H, SM_A0L, acc, wm, wn, lane);
    __syncthreads();
    loadB_async(sb, w3h, w3l, 128, 1); cpa_commit();
    cpa_wait0(); __syncthreads();
    compute_chunk(sb, SM_A1H, SM_A1L, acc, wm, wn, lane);
    __syncthreads();
}

// ---------------- cell (node) MLP kernel -------------------------------------
__global__ void __launch_bounds__(256, 2) cell_kernel(
    const __nv_bfloat16* __restrict__ xh, const __nv_bfloat16* __restrict__ xl,
    const float* __restrict__ b1, const float* __restrict__ b2, const float* __restrict__ b3,
    const float* __restrict__ gam, const float* __restrict__ bet,
    __nv_bfloat16* __restrict__ outh, __nv_bfloat16* __restrict__ outl,
    const float* __restrict__ resid, float* __restrict__ outf)
{
    extern __shared__ char smraw[];
    uint32_t sb0 = smem_u32(smraw);
    uint32_t sb = (sb0 + 1023u) & ~1023u;
    char* smA = smraw + (sb - sb0);
    int tid = threadIdx.x, lane = tid & 31, wid = tid >> 5;
    int wm = wid >> 1, wn = wid & 1;
    long row0 = (long)blockIdx.x * 128;

    auto issueA = [&](int c, int oah, int oal) {
        int seg = tid & 7, r0 = tid >> 3;
#pragma unroll
        for (int p = 0; p < 4; p++) {
            int r = p * 32 + r0;
            long gr = row0 + r;
            bool v = gr < NN;
            const __nv_bfloat16 *ph, *pl;
            if (c < 2) {
                size_t o = v ? ((size_t)gr * 128 + (size_t)c * 64 + seg * 8) : 0;
                ph = xh + o; pl = xl + o;
            } else {
                size_t o = v ? ((size_t)gr * 64 + seg * 8) : 0;
                ph = g_aggh + o; pl = g_aggl + o;
            }
            uint32_t off = swz((uint32_t)(r * 128 + seg * 16));
            cpa16(sb + oah + off, ph, v ? 16u : 0u);
            cpa16(sb + oal + off, pl, v ? 16u : 0u);
        }
        cpa_commit();
    };

    float acc[2][8][4];
    zero_acc(acc);

    issueA(0, SM_A0H, SM_A0L);
    loadB_async(sb, g_c1h, g_c1l, 192, 0); cpa_commit();
    cpa_wait0(); __syncthreads();
    issueA(1, SM_A1H, SM_A1L);                       // in flight during compute 0
    compute_chunk(sb, SM_A0H, SM_A0L, acc, wm, wn, lane);
    __syncthreads();
    loadB_async(sb, g_c1h, g_c1l, 192, 1); cpa_commit();
    cpa_wait0(); __syncthreads();
    issueA(2, SM_A0H, SM_A0L);                       // in flight during compute 1
    compute_chunk(sb, SM_A1H, SM_A1L, acc, wm, wn, lane);
    __syncthreads();
    loadB_async(sb, g_c1h, g_c1l, 192, 2); cpa_commit();
    cpa_wait0(); __syncthreads();
    compute_chunk(sb, SM_A0H, SM_A0L, acc, wm, wn, lane);

    run_l23(smA, sb, acc, g_c2h, g_c2l, g_c3h, g_c3l, b1, b2, wm, wn, lane);
    epi_ln(smA, acc, b3, gam, bet, outh, outl, resid, outf, row0, NN, wm, wn, lane);
}

// ---------------- edge MLP kernel --------------------------------------------
__global__ void __launch_bounds__(256, 2) edge_kernel(
    const __nv_bfloat16* __restrict__ eah, const __nv_bfloat16* __restrict__ eal,
    const __nv_bfloat16* __restrict__ x2h, const __nv_bfloat16* __restrict__ x2l,
    const int* __restrict__ snd, const int* __restrict__ rcv,
    const float* __restrict__ b1, const float* __restrict__ b2, const float* __restrict__ b3,
    const float* __restrict__ gam, const float* __restrict__ bet,
    const float* __restrict__ ea_resid, float* __restrict__ outf)
{
    extern __shared__ char smraw[];
    uint32_t sb0 = smem_u32(smraw);
    uint32_t sb = (sb0 + 1023u) & ~1023u;
    char* smA = smraw + (sb - sb0);
    int tid = threadIdx.x, lane = tid & 31, wid = tid >> 5;
    int wm = wid >> 1, wn = wid & 1;
    long row0 = (long)blockIdx.x * 128;

    int* sidx = reinterpret_cast<int*>(smA + SM_SIDX);
    if (tid < 128) sidx[tid] = snd[row0 + tid];
    else           sidx[tid] = rcv[row0 + tid - 128];

    auto issueA = [&](int c, int oah, int oal) {
        int seg = tid & 7, r0 = tid >> 3;
#pragma unroll
        for (int p = 0; p < 4; p++) {
            int r = p * 32 + r0;
            size_t o;
            const __nv_bfloat16 *ph, *pl;
            if (c < 2) {
                o = (size_t)(row0 + r) * 128 + (size_t)c * 64 + seg * 8;
                ph = eah + o; pl = eal + o;
            } else {
                int node = sidx[(c >= 4 ? 128 : 0) + r];
                o = (size_t)node * 128 + (size_t)(c & 1) * 64 + seg * 8;
                ph = x2h + o; pl = x2l + o;
            }
            uint32_t off = swz((uint32_t)(r * 128 + seg * 16));
            cpa16(sb + oah + off, ph, 16u);
            cpa16(sb + oal + off, pl, 16u);
        }
        cpa_commit();
    };

    float acc[2][8][4];
    zero_acc(acc);

    issueA(0, SM_A0H, SM_A0L);
    loadB_async(sb, g_e1h, g_e1l, 384, 0); cpa_commit();
    cpa_wait0(); __syncthreads();          // sidx also visible now
    issueA(1, SM_A1H, SM_A1L);
    compute_chunk(sb, SM_A0H, SM_A0L, acc, wm, wn, lane);
#pragma unroll 1
    for (int c = 1; c <= 4; c++) {
        int st = c & 1;
        __syncthreads();
        loadB_async(sb, g_e1h, g_e1l, 384, c); cpa_commit();
        cpa_wait0(); __syncthreads();
        issueA(c + 1, st ? SM_A0H : SM_A1H, st ? SM_A0L : SM_A1L);
        compute_chunk(sb, st ? SM_A1H : SM_A0H, st ? SM_A1L : SM_A0L, acc, wm, wn, lane);
    }
    __syncthreads();
    loadB_async(sb, g_e1h, g_e1l, 384, 5); cpa_commit();
    cpa_wait0(); __syncthreads();
    compute_chunk(sb, SM_A1H, SM_A1L, acc, wm, wn, lane);

    run_l23(smA, sb, acc, g_e2h, g_e2l, g_e3h, g_e3l, b1, b2, wm, wn, lane);
    epi_ln(smA, acc, b3, gam, bet, nullptr, nullptr, ea_resid, outf, row0, NE, wm, wn, lane);
}

// ---------------- scatter + conversions + weight prep ------------------------
struct WJobs {
    const float* src[6];
    __nv_bfloat16* h[6];
    __nv_bfloat16* l[6];
    int K[6];
};
__global__ void wconv_all_kernel(WJobs jobs) {
    int j = blockIdx.y;
    int K = jobs.K[j];
    int i = blockIdx.x * blockDim.x + threadIdx.x;
    if (i >= 128 * K) return;
    int n = i / K, k = i - n * K;
    float w = jobs.src[j][(size_t)k * 128 + n];
    __nv_bfloat16 h = __float2bfloat16(w);
    jobs.h[j][i] = h;
    jobs.l[j][i] = __float2bfloat16(w - __bfloat162float(h));
}

__global__ void zero_agg_kernel() {
    size_t n = (size_t)NN * 64 / 4;
    for (size_t i = (size_t)blockIdx.x * blockDim.x + threadIdx.x; i < n;
         i += (size_t)gridDim.x * blockDim.x)
        reinterpret_cast<float4*>(g_agg)[i] = make_float4(0.f, 0.f, 0.f, 0.f);
}

// scatter + fused ea -> bf16 hi/lo conversion
__global__ void __launch_bounds__(256) scatter_kernel(
    const float* __restrict__ ea, const int* __restrict__ snd, const int* __restrict__ rcv,
    __nv_bfloat16* __restrict__ eah, __nv_bfloat16* __restrict__ eal)
{
    long t = (long)blockIdx.x * blockDim.x + threadIdx.x;
    if (t >= (long)NE * 128) return;
    int e = (int)(t >> 7);
    int c = (int)(t & 127);
    float v = ea[t];
    __nv_bfloat16 h = __float2bfloat16(v);
    eah[t] = h;
    eal[t] = __float2bfloat16(v - __bfloat162float(h));
    if (c < 64) atomicAdd(&g_agg[(size_t)rcv[e] * 64 + c], v);
    else        atomicAdd(&g_agg[(size_t)snd[e] * 64 + (c - 64)], v);
}

// fp32 -> bf16 hi/lo split (pairs)
__global__ void conv_hl_kernel(const float* __restrict__ src,
                               __nv_bfloat16* __restrict__ h, __nv_bfloat16* __restrict__ l, long n2)
{
    long i = (long)blockIdx.x * blockDim.x + threadIdx.x;
    if (i >= n2) return;
    float2 v = reinterpret_cast<const float2*>(src)[i];
    __nv_bfloat162 hh = __floats2bfloat162_rn(v.x, v.y);
    float2 hf = __bfloat1622float2(hh);
    __nv_bfloat162 ll = __floats2bfloat162_rn(v.x - hf.x, v.y - hf.y);
    reinterpret_cast<__nv_bfloat162*>(h)[i] = hh;
    reinterpret_cast<__nv_bfloat162*>(l)[i] = ll;
}

// ---------------- launch -----------------------------------------------------
extern "C" void kernel_launch(void* const* d_in, const int* in_sizes, int n_in,
                              void* d_out, int out_size)
{
    const float* x       = (const float*)d_in[0];
    const float* ea      = (const float*)d_in[1];
    const float* cb_w1   = (const float*)d_in[2];
    const float* cb_b1   = (const float*)d_in[3];
    const float* cb_w2   = (const float*)d_in[4];
    const float* cb_b2   = (const float*)d_in[5];
    const float* cb_w3   = (const float*)d_in[6];
    const float* cb_b3   = (const float*)d_in[7];
    const float* cb_g    = (const float*)d_in[8];
    const float* cb_beta = (const float*)d_in[9];
    const float* eb_w1   = (const float*)d_in[10];
    const float* eb_b1   = (const float*)d_in[11];
    const float* eb_w2   = (const float*)d_in[12];
    const float* eb_b2   = (const float*)d_in[13];
    const float* eb_w3   = (const float*)d_in[14];
    const float* eb_b3   = (const float*)d_in[15];
    const float* eb_g    = (const float*)d_in[16];
    const float* eb_beta = (const float*)d_in[17];
    const int*   ei      = (const int*)d_in[18];
    const int* snd = ei;
    const int* rcv = ei + NE;

    float* out_x = (float*)d_out;
    float* out_e = out_x + (size_t)NN * 128;

    float* aggf;
    cudaGetSymbolAddress((void**)&aggf, g_agg);
    __nv_bfloat16 *xh, *xl, *x1h, *x1l, *x2h, *x2l, *aggh, *aggl, *eah, *eal;
    cudaGetSymbolAddress((void**)&xh,  g_xh);  cudaGetSymbolAddress((void**)&xl,  g_xl);
    cudaGetSymbolAddress((void**)&x1h, g_x1h); cudaGetSymbolAddress((void**)&x1l, g_x1l);
    cudaGetSymbolAddress((void**)&x2h, g_x2h); cudaGetSymbolAddress((void**)&x2l, g_x2l);
    cudaGetSymbolAddress((void**)&aggh, g_aggh); cudaGetSymbolAddress((void**)&aggl, g_aggl);
    cudaGetSymbolAddress((void**)&eah, g_eah); cudaGetSymbolAddress((void**)&eal, g_eal);

    WJobs jobs;
    const float* wsrc[6] = {cb_w1, cb_w2, cb_w3, eb_w1, eb_w2, eb_w3};
    int wk[6] = {192, 128, 128, 384, 128, 128};
    __nv_bfloat16* wh[6]; __nv_bfloat16* wl[6];
    cudaGetSymbolAddress((void**)&wh[0], g_c1h); cudaGetSymbolAddress((void**)&wl[0], g_c1l);
    cudaGetSymbolAddress((void**)&wh[1], g_c2h); cudaGetSymbolAddress((void**)&wl[1], g_c2l);
    cudaGetSymbolAddress((void**)&wh[2], g_c3h); cudaGetSymbolAddress((void**)&wl[2], g_c3l);
    cudaGetSymbolAddress((void**)&wh[3], g_e1h); cudaGetSymbolAddress((void**)&wl[3], g_e1l);
    cudaGetSymbolAddress((void**)&wh[4], g_e2h); cudaGetSymbolAddress((void**)&wl[4], g_e2l);
    cudaGetSymbolAddress((void**)&wh[5], g_e3h); cudaGetSymbolAddress((void**)&wl[5], g_e3l);
    for (int j = 0; j < 6; j++) {
        jobs.src[j] = wsrc[j]; jobs.h[j] = wh[j]; jobs.l[j] = wl[j]; jobs.K[j] = wk[j];
    }

    cudaFuncSetAttribute(cell_kernel, cudaFuncAttributeMaxDynamicSharedMemorySize, SMEM_ALLOC);
    cudaFuncSetAttribute(edge_kernel, cudaFuncAttributeMaxDynamicSharedMemorySize, SMEM_ALLOC);

    dim3 wgrid((128 * 384 + 255) / 256, 6);
    wconv_all_kernel<<<wgrid, 256>>>(jobs);                                              // 1
    conv_hl_kernel<<<(int)(((long)NN * 64 + 255) / 256), 256>>>(x, xh, xl, (long)NN * 64); // 2
    zero_agg_kernel<<<2048, 256>>>();                                                    // 3
    scatter_kernel<<<(int)(((long)NE * 128 + 255) / 256), 256>>>(ea, snd, rcv, eah, eal); // 4
    conv_hl_kernel<<<(int)(((long)NN * 32 + 255) / 256), 256>>>(aggf, aggh, aggl, (long)NN * 32); // 5

    int cell_grid = (NN + 127) / 128;   // 1563
    int edge_grid = NE / 128;           // 3125

    cell_kernel<<<cell_grid, 256, SMEM_ALLOC>>>(
        xh, xl, cb_b1, cb_b2, cb_b3, cb_g, cb_beta, x1h, x1l, nullptr, nullptr);
    cell_kernel<<<cell_grid, 256, SMEM_ALLOC>>>(
        x1h, x1l, cb_b1, cb_b2, cb_b3, cb_g, cb_beta, x2h, x2l, x, out_x);
    edge_kernel<<<edge_grid, 256, SMEM_ALLOC>>>(
        eah, eal, x2h, x2l, snd, rcv,
        eb_b1, eb_b2, eb_b3, eb_g, eb_beta, ea, out_e);
}